// round 1
// baseline (speedup 1.0000x reference)
#include <cuda_runtime.h>
#include <float.h>

// features: [B=8, X=128, Y=128, C=128] f32
// rois:     [B, N=128, 4] i32  (minX, minY, maxX, maxY)
// out:      [B, N, 7, 7, C] f32
// out[b,n,h,w,c] = max over x in xbin(w), y in ybin(h) of features[b,x,y,c]

#define PH 7
#define PW 7
#define B_ 8
#define N_ 128
#define XDIM 128
#define YDIM 128
#define CDIM 128

__global__ __launch_bounds__(CDIM, 8)
void roi_maxpool_kernel(const float* __restrict__ features,
                        const int* __restrict__ rois,
                        float* __restrict__ out)
{
    // One block per (b, n, h) strip. blockIdx.x in [0, B*N*PH)
    int bid = blockIdx.x;
    int h = bid % PH;
    int n = (bid / PH) % N_;
    int b = bid / (PH * N_);
    int c = threadIdx.x;

    const int* r = rois + ((b * N_ + n) << 2);
    int minX = r[0];
    int minY = r[1];
    int maxX = r[2];
    int maxY = r[3];

    int dx = (maxX - minX) / PW;
    int dy = (maxY - minY) / PH;

    int y0 = minY + h * dy;
    int y1 = (h == PH - 1) ? maxY : (y0 + dy);

    // base pointer for this image + channel
    const float* img = features + ((long)b * XDIM * YDIM * CDIM) + c;

    float* orow = out + ((((long)(b * N_ + n) * PH + h) * PW) * CDIM) + c;

    #pragma unroll
    for (int w = 0; w < PW; ++w) {
        int x0 = minX + w * dx;
        int x1 = (w == PW - 1) ? maxX : (x0 + dx);

        float m = -FLT_MAX;
        for (int x = x0; x < x1; ++x) {
            const float* rowp = img + ((long)x * YDIM + y0) * CDIM;
            int ylen = y1 - y0;
            int y = 0;
            // unroll by 4 for memory-level parallelism
            for (; y + 4 <= ylen; y += 4) {
                float v0 = rowp[(y + 0) * CDIM];
                float v1 = rowp[(y + 1) * CDIM];
                float v2 = rowp[(y + 2) * CDIM];
                float v3 = rowp[(y + 3) * CDIM];
                m = fmaxf(m, fmaxf(fmaxf(v0, v1), fmaxf(v2, v3)));
            }
            for (; y < ylen; ++y) {
                m = fmaxf(m, rowp[y * CDIM]);
            }
        }
        orow[w * CDIM] = m;
    }
}

extern "C" void kernel_launch(void* const* d_in, const int* in_sizes, int n_in,
                              void* d_out, int out_size)
{
    const float* features = (const float*)d_in[0];
    const int* rois = (const int*)d_in[1];
    float* out = (float*)d_out;

    dim3 grid(B_ * N_ * PH);
    dim3 block(CDIM);
    roi_maxpool_kernel<<<grid, block>>>(features, rois, out);
}

// round 2
// speedup vs baseline: 3.1656x; 3.1656x over previous
#include <cuda_runtime.h>
#include <float.h>

// features: [B=8, X=128, Y=128, C=128] f32   (C contiguous)
// rois:     [B, N=128, 4] i32  (minX, minY, maxX, maxY)
// out:      [B, N, 7, 7, C] f32
// out[b,n,h,w,c] = max over x in xbin(w), y in ybin(h) of features[b,x,y,c]

#define PH 7
#define PW 7
#define B_ 8
#define N_ 128
#define XDIM 128
#define YDIM 128
#define CDIM 128
#define C4   (CDIM / 4)   // 32 float4 per pixel

__device__ __forceinline__ float4 f4max(float4 a, float4 b) {
    return make_float4(fmaxf(a.x, b.x), fmaxf(a.y, b.y),
                       fmaxf(a.z, b.z), fmaxf(a.w, b.w));
}

__global__ __launch_bounds__(PW * 32)
void roi_maxpool_kernel(const float4* __restrict__ features,
                        const int4*   __restrict__ rois,
                        float4*       __restrict__ out)
{
    // one block per (b, n, h); one warp per w-bin
    int bid  = blockIdx.x;
    int h    = bid % PH;
    int n    = (bid / PH) % N_;
    int b    = bid / (PH * N_);
    int w    = threadIdx.x >> 5;
    int lane = threadIdx.x & 31;

    const int4 r = rois[b * N_ + n];
    int minX = r.x, minY = r.y, maxX = r.z, maxY = r.w;

    int dx = (maxX - minX) / PW;
    int dy = (maxY - minY) / PH;

    int y0 = minY + h * dy;
    int y1 = (h == PH - 1) ? maxY : (y0 + dy);
    int x0 = minX + w * dx;
    int x1 = (w == PW - 1) ? maxX : (x0 + dx);
    int ny = y1 - y0;

    const float4 NEG = make_float4(-FLT_MAX, -FLT_MAX, -FLT_MAX, -FLT_MAX);
    float4 m0 = NEG;
    float4 m1 = NEG;

    // index of [b, x, y, c4] = ((b*XDIM + x)*YDIM + y)*C4 + c4
    const long img_base = (long)b * XDIM * YDIM * C4;
    const long col_stride = (long)YDIM * C4;   // +1 in x

    int x = x0;
    // process two x-columns at a time (independent load streams)
    for (; x + 2 <= x1; x += 2) {
        const float4* p0 = features + img_base + (long)x * col_stride + (long)y0 * C4 + lane;
        const float4* p1 = p0 + col_stride;
        int y = 0;
        for (; y + 4 <= ny; y += 4) {
            float4 a0 = p0[(y + 0) * C4];
            float4 a1 = p0[(y + 1) * C4];
            float4 a2 = p0[(y + 2) * C4];
            float4 a3 = p0[(y + 3) * C4];
            float4 b0 = p1[(y + 0) * C4];
            float4 b1 = p1[(y + 1) * C4];
            float4 b2 = p1[(y + 2) * C4];
            float4 b3 = p1[(y + 3) * C4];
            m0 = f4max(m0, f4max(f4max(a0, a1), f4max(a2, a3)));
            m1 = f4max(m1, f4max(f4max(b0, b1), f4max(b2, b3)));
        }
        for (; y < ny; ++y) {
            m0 = f4max(m0, p0[y * C4]);
            m1 = f4max(m1, p1[y * C4]);
        }
    }
    // remainder single x-column
    if (x < x1) {
        const float4* p0 = features + img_base + (long)x * col_stride + (long)y0 * C4 + lane;
        int y = 0;
        for (; y + 4 <= ny; y += 4) {
            float4 a0 = p0[(y + 0) * C4];
            float4 a1 = p0[(y + 1) * C4];
            float4 a2 = p0[(y + 2) * C4];
            float4 a3 = p0[(y + 3) * C4];
            m0 = f4max(m0, f4max(f4max(a0, a1), f4max(a2, a3)));
        }
        for (; y < ny; ++y) {
            m0 = f4max(m0, p0[y * C4]);
        }
    }

    float4 m = f4max(m0, m1);

    long oidx = ((((long)(b * N_ + n) * PH + h) * PW + w) * C4) + lane;
    out[oidx] = m;
}

extern "C" void kernel_launch(void* const* d_in, const int* in_sizes, int n_in,
                              void* d_out, int out_size)
{
    const float4* features = (const float4*)d_in[0];
    const int4*   rois     = (const int4*)d_in[1];
    float4*       out      = (float4*)d_out;

    dim3 grid(B_ * N_ * PH);
    dim3 block(PW * 32);
    roi_maxpool_kernel<<<grid, block>>>(features, rois, out);
}